// round 5
// baseline (speedup 1.0000x reference)
#include <cuda_runtime.h>
#include <cstdint>

#define OUT_F  4096
#define IN_F   4096
#define NFREQ  10000
#define ROWS   1024          // 2 * 512
#define SCALE  2.34375f      // 150 / sqrt(4096)

// Scratch (static __device__ arrays — no allocation allowed)
static __device__ float    g_y[(size_t)ROWS * OUT_F];   // 16 MB: X·dense^T, then WHT'd
static __device__ unsigned g_key[NFREQ];
static __device__ int      g_valid[NFREQ];
static __device__ int      g_o[NFREQ];
static __device__ int      g_i[NFREQ];
static __device__ int      g_is32;

// ---------------------------------------------------------------------------
// 0) reset dtype flag (must be deterministic per replay)
__global__ void k_reset() {
    if (threadIdx.x == 0 && blockIdx.x == 0) g_is32 = 0;
}

// 0b) detect indices dtype. Reading NFREQ int64 = 80000 bytes, which is exactly
//     the buffer size under the int32 interpretation (2*NFREQ*4) — safe either way.
//     True int64 data: all values in [0, 4096). int32 data read as int64: high
//     word is the next index (nonzero w.p. 4095/4096) -> value >= 2^32.
__global__ void k_detect(const long long* __restrict__ idx) {
    int k = blockIdx.x * blockDim.x + threadIdx.x;
    if (k < NFREQ) {
        unsigned long long v = (unsigned long long)idx[k];
        if (v >= (unsigned long long)OUT_F) atomicOr(&g_is32, 1);
    }
}

// 1) decode (o, i) per entry under the detected dtype; pack dedupe keys.
__global__ void k_key(const void* __restrict__ idxv) {
    int k = blockIdx.x * blockDim.x + threadIdx.x;
    if (k >= NFREQ) return;
    int o, i;
    if (g_is32) {
        const int* p = (const int*)idxv;
        o = p[k];
        i = p[NFREQ + k];
    } else {
        const long long* p = (const long long*)idxv;
        o = (int)p[k];
        i = (int)p[NFREQ + k];
    }
    o &= (OUT_F - 1);                 // defensive: never index OOB
    i &= (IN_F - 1);
    g_o[k] = o;
    g_i[k] = i;
    g_key[k] = (unsigned)o * (unsigned)IN_F + (unsigned)i;
}

// 2) dedupe: entry k valid iff no LATER entry has the same (o,i)
//    (last update wins, matching sequential scatter .set semantics).
__global__ void k_dedupe() {
    int k = blockIdx.x * blockDim.x + threadIdx.x;
    if (k >= NFREQ) return;
    unsigned key = g_key[k];
    int v = 1;
    for (int j = k + 1; j < NFREQ; ++j) {
        if (g_key[j] == key) { v = 0; break; }
    }
    g_valid[k] = v;
}

// 3) zero y (must re-zero every graph replay)
__global__ void k_zero() {
    size_t t = (size_t)blockIdx.x * blockDim.x + threadIdx.x;
    reinterpret_cast<float4*>(g_y)[t] = make_float4(0.f, 0.f, 0.f, 0.f);
}

// 4) sparse contraction: y[r, o_k] += x[r, i_k] * s_k   for valid k
__global__ void k_scatter(const float* __restrict__ x,
                          const float* __restrict__ spec) {
    int k = blockIdx.y;
    if (!g_valid[k]) return;
    int r = blockIdx.x * blockDim.x + threadIdx.x;   // 0..1023
    int o = g_o[k];
    int i = g_i[k];
    float s = spec[k];
    atomicAdd(&g_y[(size_t)r * OUT_F + o], x[(size_t)r * IN_F + i] * s);
}

// 5) in-place 4096-pt Walsh-Hadamard transform along o, per row, then * SCALE.
//    Butterfly stages over distinct bits commute, so stage order matches iwht.
__global__ void k_wht() {
    __shared__ __align__(16) float s[OUT_F];
    int r = blockIdx.x;
    float* yr = g_y + (size_t)r * OUT_F;
    for (int j = threadIdx.x; j < OUT_F; j += blockDim.x) s[j] = yr[j];
    __syncthreads();
    for (int len = 1; len < OUT_F; len <<= 1) {
        for (int p = threadIdx.x; p < OUT_F / 2; p += blockDim.x) {
            int i0 = 2 * p - (p & (len - 1));
            int i1 = i0 + len;
            float a = s[i0], b = s[i1];
            s[i0] = a + b;
            s[i1] = a - b;
        }
        __syncthreads();
    }
    for (int j = threadIdx.x; j < OUT_F; j += blockDim.x) yr[j] = s[j] * SCALE;
}

// 6) GEMM (NT): out[r, o] = sum_i x[r,i] * w[o,i]  +  y_wht[r, o]
//    128x128 tile, BK=8, 256 threads, 8x8 microtile per thread.
__global__ __launch_bounds__(256)
void k_gemm(const float* __restrict__ x,
            const float* __restrict__ w,
            float* __restrict__ out) {
    __shared__ __align__(16) float Xs[8][128];
    __shared__ __align__(16) float Ws[8][128];

    const int bn = blockIdx.x;             // 0..31  (o tiles)
    const int bm = blockIdx.y;             // 0..7   (row tiles)
    const int tid = threadIdx.x;
    const int tx = tid & 15;               // n sub-tile
    const int ty = tid >> 4;               // m sub-tile

    const float* xg = x + (size_t)bm * 128 * IN_F;
    const float* wg = w + (size_t)bn * 128 * IN_F;

    const int lrow = tid >> 1;             // 0..127
    const int lcol = (tid & 1) * 4;        // 0 or 4

    float acc[8][8];
    #pragma unroll
    for (int m = 0; m < 8; ++m)
        #pragma unroll
        for (int n = 0; n < 8; ++n) acc[m][n] = 0.f;

    for (int kk = 0; kk < IN_F; kk += 8) {
        float4 xv = *reinterpret_cast<const float4*>(xg + (size_t)lrow * IN_F + kk + lcol);
        float4 wv = *reinterpret_cast<const float4*>(wg + (size_t)lrow * IN_F + kk + lcol);
        Xs[lcol + 0][lrow] = xv.x; Xs[lcol + 1][lrow] = xv.y;
        Xs[lcol + 2][lrow] = xv.z; Xs[lcol + 3][lrow] = xv.w;
        Ws[lcol + 0][lrow] = wv.x; Ws[lcol + 1][lrow] = wv.y;
        Ws[lcol + 2][lrow] = wv.z; Ws[lcol + 3][lrow] = wv.w;
        __syncthreads();

        #pragma unroll
        for (int k = 0; k < 8; ++k) {
            float xf[8], wf[8];
            *reinterpret_cast<float4*>(&xf[0]) = *reinterpret_cast<const float4*>(&Xs[k][ty * 8]);
            *reinterpret_cast<float4*>(&xf[4]) = *reinterpret_cast<const float4*>(&Xs[k][ty * 8 + 4]);
            *reinterpret_cast<float4*>(&wf[0]) = *reinterpret_cast<const float4*>(&Ws[k][tx * 8]);
            *reinterpret_cast<float4*>(&wf[4]) = *reinterpret_cast<const float4*>(&Ws[k][tx * 8 + 4]);
            #pragma unroll
            for (int m = 0; m < 8; ++m)
                #pragma unroll
                for (int n = 0; n < 8; ++n)
                    acc[m][n] = fmaf(xf[m], wf[n], acc[m][n]);
        }
        __syncthreads();
    }

    const int r0 = bm * 128 + ty * 8;
    const int c0 = bn * 128 + tx * 8;
    #pragma unroll
    for (int m = 0; m < 8; ++m) {
        size_t base = (size_t)(r0 + m) * OUT_F + c0;
        #pragma unroll
        for (int nq = 0; nq < 2; ++nq) {
            float4 yv = *reinterpret_cast<const float4*>(&g_y[base + nq * 4]);
            float4 ov;
            ov.x = acc[m][nq * 4 + 0] + yv.x;
            ov.y = acc[m][nq * 4 + 1] + yv.y;
            ov.z = acc[m][nq * 4 + 2] + yv.z;
            ov.w = acc[m][nq * 4 + 3] + yv.w;
            *reinterpret_cast<float4*>(&out[base + nq * 4]) = ov;
        }
    }
}

// ---------------------------------------------------------------------------
extern "C" void kernel_launch(void* const* d_in, const int* in_sizes, int n_in,
                              void* d_out, int out_size) {
    const float* x    = (const float*)d_in[0];   // [2,512,4096]
    const float* w    = (const float*)d_in[1];   // [4096,4096]
    const float* spec = (const float*)d_in[2];   // [10000]
    const void*  idx  = d_in[3];                 // [2,10000] int32 or int64
    float* out = (float*)d_out;                  // [2,512,4096]
    (void)in_sizes; (void)n_in; (void)out_size;

    k_reset <<<1, 32>>>();
    k_detect<<<(NFREQ + 255) / 256, 256>>>((const long long*)idx);
    k_key   <<<(NFREQ + 255) / 256, 256>>>(idx);
    k_dedupe<<<(NFREQ + 255) / 256, 256>>>();
    k_zero  <<<((size_t)ROWS * OUT_F / 4) / 256, 256>>>();
    k_scatter<<<dim3(ROWS / 256, NFREQ), 256>>>(x, spec);
    k_wht   <<<ROWS, 256>>>();
    k_gemm  <<<dim3(OUT_F / 128, ROWS / 128), 256>>>(x, w, out);
}

// round 6
// speedup vs baseline: 1.0007x; 1.0007x over previous
#include <cuda_runtime.h>
#include <cstdint>

#define OUT_F  4096
#define IN_F   4096
#define NFREQ  10000
#define ROWS   1024          // 2 * 512
#define SCALE  2.34375f      // 150 / sqrt(4096)

// Scratch (static __device__ arrays — no allocation allowed)
static __device__ float    g_y[(size_t)ROWS * OUT_F];   // 16 MB: X·dense^T, then WHT'd
static __device__ unsigned g_key[NFREQ];
static __device__ int      g_valid[NFREQ];
static __device__ int      g_o[NFREQ];
static __device__ int      g_i[NFREQ];
static __device__ int      g_is32;

// ---------------------------------------------------------------------------
// 0) reset dtype flag (must be deterministic per replay)
__global__ void k_reset() {
    if (threadIdx.x == 0 && blockIdx.x == 0) g_is32 = 0;
}

// 0b) detect indices dtype. Reading NFREQ int64 = 80000 bytes, which is exactly
//     the buffer size under the int32 interpretation (2*NFREQ*4) — safe either way.
//     True int64 data: all values in [0, 4096). int32 data read as int64: high
//     word is the next index (nonzero w.p. 4095/4096) -> value >= 2^32.
__global__ void k_detect(const long long* __restrict__ idx) {
    int k = blockIdx.x * blockDim.x + threadIdx.x;
    if (k < NFREQ) {
        unsigned long long v = (unsigned long long)idx[k];
        if (v >= (unsigned long long)OUT_F) atomicOr(&g_is32, 1);
    }
}

// 1) decode (o, i) per entry under the detected dtype; pack dedupe keys.
__global__ void k_key(const void* __restrict__ idxv) {
    int k = blockIdx.x * blockDim.x + threadIdx.x;
    if (k >= NFREQ) return;
    int o, i;
    if (g_is32) {
        const int* p = (const int*)idxv;
        o = p[k];
        i = p[NFREQ + k];
    } else {
        const long long* p = (const long long*)idxv;
        o = (int)p[k];
        i = (int)p[NFREQ + k];
    }
    o &= (OUT_F - 1);                 // defensive: never index OOB
    i &= (IN_F - 1);
    g_o[k] = o;
    g_i[k] = i;
    g_key[k] = (unsigned)o * (unsigned)IN_F + (unsigned)i;
}

// 2) dedupe: entry k valid iff no LATER entry has the same (o,i)
//    (last update wins, matching sequential scatter .set semantics).
__global__ void k_dedupe() {
    int k = blockIdx.x * blockDim.x + threadIdx.x;
    if (k >= NFREQ) return;
    unsigned key = g_key[k];
    int v = 1;
    for (int j = k + 1; j < NFREQ; ++j) {
        if (g_key[j] == key) { v = 0; break; }
    }
    g_valid[k] = v;
}

// 3) zero y (must re-zero every graph replay)
__global__ void k_zero() {
    size_t t = (size_t)blockIdx.x * blockDim.x + threadIdx.x;
    reinterpret_cast<float4*>(g_y)[t] = make_float4(0.f, 0.f, 0.f, 0.f);
}

// 4) sparse contraction: y[r, o_k] += x[r, i_k] * s_k   for valid k
__global__ void k_scatter(const float* __restrict__ x,
                          const float* __restrict__ spec) {
    int k = blockIdx.y;
    if (!g_valid[k]) return;
    int r = blockIdx.x * blockDim.x + threadIdx.x;   // 0..1023
    int o = g_o[k];
    int i = g_i[k];
    float s = spec[k];
    atomicAdd(&g_y[(size_t)r * OUT_F + o], x[(size_t)r * IN_F + i] * s);
}

// 5) in-place 4096-pt Walsh-Hadamard transform along o, per row, then * SCALE.
//    Butterfly stages over distinct bits commute, so stage order matches iwht.
__global__ void k_wht() {
    __shared__ __align__(16) float s[OUT_F];
    int r = blockIdx.x;
    float* yr = g_y + (size_t)r * OUT_F;
    for (int j = threadIdx.x; j < OUT_F; j += blockDim.x) s[j] = yr[j];
    __syncthreads();
    for (int len = 1; len < OUT_F; len <<= 1) {
        for (int p = threadIdx.x; p < OUT_F / 2; p += blockDim.x) {
            int i0 = 2 * p - (p & (len - 1));
            int i1 = i0 + len;
            float a = s[i0], b = s[i1];
            s[i0] = a + b;
            s[i1] = a - b;
        }
        __syncthreads();
    }
    for (int j = threadIdx.x; j < OUT_F; j += blockDim.x) yr[j] = s[j] * SCALE;
}

// 6) GEMM (NT): out[r, o] = sum_i x[r,i] * w[o,i]  +  y_wht[r, o]
//    128x128 tile, BK=8, 256 threads, 8x8 microtile per thread.
__global__ __launch_bounds__(256)
void k_gemm(const float* __restrict__ x,
            const float* __restrict__ w,
            float* __restrict__ out) {
    __shared__ __align__(16) float Xs[8][128];
    __shared__ __align__(16) float Ws[8][128];

    const int bn = blockIdx.x;             // 0..31  (o tiles)
    const int bm = blockIdx.y;             // 0..7   (row tiles)
    const int tid = threadIdx.x;
    const int tx = tid & 15;               // n sub-tile
    const int ty = tid >> 4;               // m sub-tile

    const float* xg = x + (size_t)bm * 128 * IN_F;
    const float* wg = w + (size_t)bn * 128 * IN_F;

    const int lrow = tid >> 1;             // 0..127
    const int lcol = (tid & 1) * 4;        // 0 or 4

    float acc[8][8];
    #pragma unroll
    for (int m = 0; m < 8; ++m)
        #pragma unroll
        for (int n = 0; n < 8; ++n) acc[m][n] = 0.f;

    for (int kk = 0; kk < IN_F; kk += 8) {
        float4 xv = *reinterpret_cast<const float4*>(xg + (size_t)lrow * IN_F + kk + lcol);
        float4 wv = *reinterpret_cast<const float4*>(wg + (size_t)lrow * IN_F + kk + lcol);
        Xs[lcol + 0][lrow] = xv.x; Xs[lcol + 1][lrow] = xv.y;
        Xs[lcol + 2][lrow] = xv.z; Xs[lcol + 3][lrow] = xv.w;
        Ws[lcol + 0][lrow] = wv.x; Ws[lcol + 1][lrow] = wv.y;
        Ws[lcol + 2][lrow] = wv.z; Ws[lcol + 3][lrow] = wv.w;
        __syncthreads();

        #pragma unroll
        for (int k = 0; k < 8; ++k) {
            float xf[8], wf[8];
            *reinterpret_cast<float4*>(&xf[0]) = *reinterpret_cast<const float4*>(&Xs[k][ty * 8]);
            *reinterpret_cast<float4*>(&xf[4]) = *reinterpret_cast<const float4*>(&Xs[k][ty * 8 + 4]);
            *reinterpret_cast<float4*>(&wf[0]) = *reinterpret_cast<const float4*>(&Ws[k][tx * 8]);
            *reinterpret_cast<float4*>(&wf[4]) = *reinterpret_cast<const float4*>(&Ws[k][tx * 8 + 4]);
            #pragma unroll
            for (int m = 0; m < 8; ++m)
                #pragma unroll
                for (int n = 0; n < 8; ++n)
                    acc[m][n] = fmaf(xf[m], wf[n], acc[m][n]);
        }
        __syncthreads();
    }

    const int r0 = bm * 128 + ty * 8;
    const int c0 = bn * 128 + tx * 8;
    #pragma unroll
    for (int m = 0; m < 8; ++m) {
        size_t base = (size_t)(r0 + m) * OUT_F + c0;
        #pragma unroll
        for (int nq = 0; nq < 2; ++nq) {
            float4 yv = *reinterpret_cast<const float4*>(&g_y[base + nq * 4]);
            float4 ov;
            ov.x = acc[m][nq * 4 + 0] + yv.x;
            ov.y = acc[m][nq * 4 + 1] + yv.y;
            ov.z = acc[m][nq * 4 + 2] + yv.z;
            ov.w = acc[m][nq * 4 + 3] + yv.w;
            *reinterpret_cast<float4*>(&out[base + nq * 4]) = ov;
        }
    }
}

// ---------------------------------------------------------------------------
extern "C" void kernel_launch(void* const* d_in, const int* in_sizes, int n_in,
                              void* d_out, int out_size) {
    const float* x    = (const float*)d_in[0];   // [2,512,4096]
    const float* w    = (const float*)d_in[1];   // [4096,4096]
    const float* spec = (const float*)d_in[2];   // [10000]
    const void*  idx  = d_in[3];                 // [2,10000] int32 or int64
    float* out = (float*)d_out;                  // [2,512,4096]
    (void)in_sizes; (void)n_in; (void)out_size;

    k_reset <<<1, 32>>>();
    k_detect<<<(NFREQ + 255) / 256, 256>>>((const long long*)idx);
    k_key   <<<(NFREQ + 255) / 256, 256>>>(idx);
    k_dedupe<<<(NFREQ + 255) / 256, 256>>>();
    k_zero  <<<((size_t)ROWS * OUT_F / 4) / 256, 256>>>();
    k_scatter<<<dim3(ROWS / 256, NFREQ), 256>>>(x, spec);
    k_wht   <<<ROWS, 256>>>();
    k_gemm  <<<dim3(OUT_F / 128, ROWS / 128), 256>>>(x, w, out);
}

// round 7
// speedup vs baseline: 1.0066x; 1.0059x over previous
#include <cuda_runtime.h>
#include <cstdint>

#define OUT_F  4096
#define IN_F   4096
#define NFREQ  10000
#define ROWS   1024          // 2 * 512
#define SCALE  2.34375f      // 150 / sqrt(4096)

// Scratch (static __device__ arrays — no allocation allowed)
static __device__ float    g_y[(size_t)ROWS * OUT_F];   // 16 MB: X·dense^T, then WHT'd
static __device__ unsigned g_key[NFREQ];
static __device__ int      g_valid[NFREQ];
static __device__ int      g_o[NFREQ];
static __device__ int      g_i[NFREQ];
static __device__ int      g_is32;

// ---------------------------------------------------------------------------
// 0) reset dtype flag (must be deterministic per replay)
__global__ void k_reset() {
    if (threadIdx.x == 0 && blockIdx.x == 0) g_is32 = 0;
}

// 0b) detect indices dtype. Reading NFREQ int64 = 80000 bytes, which is exactly
//     the buffer size under the int32 interpretation (2*NFREQ*4) — safe either way.
//     True int64 data: all values in [0, 4096). int32 data read as int64: high
//     word is the next index (nonzero w.p. 4095/4096) -> value >= 2^32.
__global__ void k_detect(const long long* __restrict__ idx) {
    int k = blockIdx.x * blockDim.x + threadIdx.x;
    if (k < NFREQ) {
        unsigned long long v = (unsigned long long)idx[k];
        if (v >= (unsigned long long)OUT_F) atomicOr(&g_is32, 1);
    }
}

// 1) decode (o, i) per entry under the detected dtype; pack dedupe keys.
__global__ void k_key(const void* __restrict__ idxv) {
    int k = blockIdx.x * blockDim.x + threadIdx.x;
    if (k >= NFREQ) return;
    int o, i;
    if (g_is32) {
        const int* p = (const int*)idxv;
        o = p[k];
        i = p[NFREQ + k];
    } else {
        const long long* p = (const long long*)idxv;
        o = (int)p[k];
        i = (int)p[NFREQ + k];
    }
    o &= (OUT_F - 1);                 // defensive: never index OOB
    i &= (IN_F - 1);
    g_o[k] = o;
    g_i[k] = i;
    g_key[k] = (unsigned)o * (unsigned)IN_F + (unsigned)i;
}

// 2) dedupe: entry k valid iff no LATER entry has the same (o,i)
//    (last update wins, matching sequential scatter .set semantics).
__global__ void k_dedupe() {
    int k = blockIdx.x * blockDim.x + threadIdx.x;
    if (k >= NFREQ) return;
    unsigned key = g_key[k];
    int v = 1;
    for (int j = k + 1; j < NFREQ; ++j) {
        if (g_key[j] == key) { v = 0; break; }
    }
    g_valid[k] = v;
}

// 3) zero y (must re-zero every graph replay)
__global__ void k_zero() {
    size_t t = (size_t)blockIdx.x * blockDim.x + threadIdx.x;
    reinterpret_cast<float4*>(g_y)[t] = make_float4(0.f, 0.f, 0.f, 0.f);
}

// 4) sparse contraction: y[r, o_k] += x[r, i_k] * s_k   for valid k
__global__ void k_scatter(const float* __restrict__ x,
                          const float* __restrict__ spec) {
    int k = blockIdx.y;
    if (!g_valid[k]) return;
    int r = blockIdx.x * blockDim.x + threadIdx.x;   // 0..1023
    int o = g_o[k];
    int i = g_i[k];
    float s = spec[k];
    atomicAdd(&g_y[(size_t)r * OUT_F + o], x[(size_t)r * IN_F + i] * s);
}

// 5) in-place 4096-pt Walsh-Hadamard transform along o, per row, then * SCALE.
//    Butterfly stages over distinct bits commute, so stage order matches iwht.
__global__ void k_wht() {
    __shared__ __align__(16) float s[OUT_F];
    int r = blockIdx.x;
    float* yr = g_y + (size_t)r * OUT_F;
    for (int j = threadIdx.x; j < OUT_F; j += blockDim.x) s[j] = yr[j];
    __syncthreads();
    for (int len = 1; len < OUT_F; len <<= 1) {
        for (int p = threadIdx.x; p < OUT_F / 2; p += blockDim.x) {
            int i0 = 2 * p - (p & (len - 1));
            int i1 = i0 + len;
            float a = s[i0], b = s[i1];
            s[i0] = a + b;
            s[i1] = a - b;
        }
        __syncthreads();
    }
    for (int j = threadIdx.x; j < OUT_F; j += blockDim.x) yr[j] = s[j] * SCALE;
}

// 6) GEMM (NT): out[r, o] = sum_i x[r,i] * w[o,i]  +  y_wht[r, o]
//    128x128 tile, BK=8, 256 threads, 8x8 microtile per thread.
__global__ __launch_bounds__(256)
void k_gemm(const float* __restrict__ x,
            const float* __restrict__ w,
            float* __restrict__ out) {
    __shared__ __align__(16) float Xs[8][128];
    __shared__ __align__(16) float Ws[8][128];

    const int bn = blockIdx.x;             // 0..31  (o tiles)
    const int bm = blockIdx.y;             // 0..7   (row tiles)
    const int tid = threadIdx.x;
    const int tx = tid & 15;               // n sub-tile
    const int ty = tid >> 4;               // m sub-tile

    const float* xg = x + (size_t)bm * 128 * IN_F;
    const float* wg = w + (size_t)bn * 128 * IN_F;

    const int lrow = tid >> 1;             // 0..127
    const int lcol = (tid & 1) * 4;        // 0 or 4

    float acc[8][8];
    #pragma unroll
    for (int m = 0; m < 8; ++m)
        #pragma unroll
        for (int n = 0; n < 8; ++n) acc[m][n] = 0.f;

    for (int kk = 0; kk < IN_F; kk += 8) {
        float4 xv = *reinterpret_cast<const float4*>(xg + (size_t)lrow * IN_F + kk + lcol);
        float4 wv = *reinterpret_cast<const float4*>(wg + (size_t)lrow * IN_F + kk + lcol);
        Xs[lcol + 0][lrow] = xv.x; Xs[lcol + 1][lrow] = xv.y;
        Xs[lcol + 2][lrow] = xv.z; Xs[lcol + 3][lrow] = xv.w;
        Ws[lcol + 0][lrow] = wv.x; Ws[lcol + 1][lrow] = wv.y;
        Ws[lcol + 2][lrow] = wv.z; Ws[lcol + 3][lrow] = wv.w;
        __syncthreads();

        #pragma unroll
        for (int k = 0; k < 8; ++k) {
            float xf[8], wf[8];
            *reinterpret_cast<float4*>(&xf[0]) = *reinterpret_cast<const float4*>(&Xs[k][ty * 8]);
            *reinterpret_cast<float4*>(&xf[4]) = *reinterpret_cast<const float4*>(&Xs[k][ty * 8 + 4]);
            *reinterpret_cast<float4*>(&wf[0]) = *reinterpret_cast<const float4*>(&Ws[k][tx * 8]);
            *reinterpret_cast<float4*>(&wf[4]) = *reinterpret_cast<const float4*>(&Ws[k][tx * 8 + 4]);
            #pragma unroll
            for (int m = 0; m < 8; ++m)
                #pragma unroll
                for (int n = 0; n < 8; ++n)
                    acc[m][n] = fmaf(xf[m], wf[n], acc[m][n]);
        }
        __syncthreads();
    }

    const int r0 = bm * 128 + ty * 8;
    const int c0 = bn * 128 + tx * 8;
    #pragma unroll
    for (int m = 0; m < 8; ++m) {
        size_t base = (size_t)(r0 + m) * OUT_F + c0;
        #pragma unroll
        for (int nq = 0; nq < 2; ++nq) {
            float4 yv = *reinterpret_cast<const float4*>(&g_y[base + nq * 4]);
            float4 ov;
            ov.x = acc[m][nq * 4 + 0] + yv.x;
            ov.y = acc[m][nq * 4 + 1] + yv.y;
            ov.z = acc[m][nq * 4 + 2] + yv.z;
            ov.w = acc[m][nq * 4 + 3] + yv.w;
            *reinterpret_cast<float4*>(&out[base + nq * 4]) = ov;
        }
    }
}

// ---------------------------------------------------------------------------
extern "C" void kernel_launch(void* const* d_in, const int* in_sizes, int n_in,
                              void* d_out, int out_size) {
    const float* x    = (const float*)d_in[0];   // [2,512,4096]
    const float* w    = (const float*)d_in[1];   // [4096,4096]
    const float* spec = (const float*)d_in[2];   // [10000]
    const void*  idx  = d_in[3];                 // [2,10000] int32 or int64
    float* out = (float*)d_out;                  // [2,512,4096]
    (void)in_sizes; (void)n_in; (void)out_size;

    k_reset <<<1, 32>>>();
    k_detect<<<(NFREQ + 255) / 256, 256>>>((const long long*)idx);
    k_key   <<<(NFREQ + 255) / 256, 256>>>(idx);
    k_dedupe<<<(NFREQ + 255) / 256, 256>>>();
    k_zero  <<<((size_t)ROWS * OUT_F / 4) / 256, 256>>>();
    k_scatter<<<dim3(ROWS / 256, NFREQ), 256>>>(x, spec);
    k_wht   <<<ROWS, 256>>>();
    k_gemm  <<<dim3(OUT_F / 128, ROWS / 128), 256>>>(x, w, out);
}

// round 8
// speedup vs baseline: 1.6315x; 1.6208x over previous
#include <cuda_runtime.h>
#include <cstdint>

#define OUT_F  4096
#define IN_F   4096
#define NFREQ  10000
#define ROWS   1024          // 2 * 512
#define SCALE  2.34375f      // 150 / sqrt(4096)

// Scratch (static __device__ arrays — no allocation allowed)
static __device__ float    g_y[(size_t)ROWS * OUT_F];        // 16 MB
static __device__ int      g_last[(size_t)OUT_F * IN_F];     // 64 MB hash (only 10k slots touched)
static __device__ unsigned g_key[NFREQ];
static __device__ int      g_valid[NFREQ];
static __device__ int      g_o[NFREQ];
static __device__ int      g_i[NFREQ];
static __device__ int      g_is32;

// ---------------------------------------------------------------------------
__global__ void k_reset() {
    if (threadIdx.x == 0 && blockIdx.x == 0) g_is32 = 0;
}

// Detect indices dtype (int32 vs int64). Reading NFREQ int64 = 80000 bytes is
// exactly the int32-interpretation buffer size — safe either way.
__global__ void k_detect(const long long* __restrict__ idx) {
    int k = blockIdx.x * blockDim.x + threadIdx.x;
    if (k < NFREQ) {
        unsigned long long v = (unsigned long long)idx[k];
        if (v >= (unsigned long long)OUT_F) atomicOr(&g_is32, 1);
    }
}

// Decode (o, i) under detected dtype; pack keys.
__global__ void k_key(const void* __restrict__ idxv) {
    int k = blockIdx.x * blockDim.x + threadIdx.x;
    if (k >= NFREQ) return;
    int o, i;
    if (g_is32) {
        const int* p = (const int*)idxv;
        o = p[k];           i = p[NFREQ + k];
    } else {
        const long long* p = (const long long*)idxv;
        o = (int)p[k];      i = (int)p[NFREQ + k];
    }
    o &= (OUT_F - 1);
    i &= (IN_F - 1);
    g_o[k] = o;
    g_i[k] = i;
    g_key[k] = (unsigned)o * (unsigned)IN_F + (unsigned)i;
}

// Dedupe via direct-mapped table, O(N). Clear only touched slots (graph-replay
// safe), take max entry index per key (last update wins), mark winners.
__global__ void k_hclear() {
    int k = blockIdx.x * blockDim.x + threadIdx.x;
    if (k < NFREQ) g_last[g_key[k]] = 0;
}
__global__ void k_hfill() {
    int k = blockIdx.x * blockDim.x + threadIdx.x;
    if (k < NFREQ) atomicMax(&g_last[g_key[k]], k + 1);
}
__global__ void k_hvalid() {
    int k = blockIdx.x * blockDim.x + threadIdx.x;
    if (k < NFREQ) g_valid[k] = (g_last[g_key[k]] == k + 1);
}

// Zero y (every replay)
__global__ void k_zero() {
    size_t t = (size_t)blockIdx.x * blockDim.x + threadIdx.x;
    reinterpret_cast<float4*>(g_y)[t] = make_float4(0.f, 0.f, 0.f, 0.f);
}

// Sparse contraction: y[r, o_k] += x[r, i_k] * s_k for valid k
__global__ void k_scatter(const float* __restrict__ x,
                          const float* __restrict__ spec) {
    int k = blockIdx.y;
    if (!g_valid[k]) return;
    int r = blockIdx.x * blockDim.x + threadIdx.x;   // 0..1023
    int o = g_o[k];
    int i = g_i[k];
    float s = spec[k];
    atomicAdd(&g_y[(size_t)r * OUT_F + o], x[(size_t)r * IN_F + i] * s);
}

// In-place 4096-pt WHT along o per row, then * SCALE.
__global__ void k_wht() {
    __shared__ __align__(16) float s[OUT_F];
    int r = blockIdx.x;
    float* yr = g_y + (size_t)r * OUT_F;
    for (int j = threadIdx.x; j < OUT_F; j += blockDim.x) s[j] = yr[j];
    __syncthreads();
    for (int len = 1; len < OUT_F; len <<= 1) {
        for (int p = threadIdx.x; p < OUT_F / 2; p += blockDim.x) {
            int i0 = 2 * p - (p & (len - 1));
            int i1 = i0 + len;
            float a = s[i0], b = s[i1];
            s[i0] = a + b;
            s[i1] = a - b;
        }
        __syncthreads();
    }
    for (int j = threadIdx.x; j < OUT_F; j += blockDim.x) yr[j] = s[j] * SCALE;
}

// GEMM (NT), double-buffered: out[r,o] = sum_i x[r,i]*w[o,i] + y_wht[r,o]
// 128x128 tile, BK=8, 256 threads, 8x8 microtile, 1 sync per stage.
#define SPAD 132   // padded row stride (floats), 16B-aligned, kills store conflicts
__global__ __launch_bounds__(256)
void k_gemm(const float* __restrict__ x,
            const float* __restrict__ w,
            float* __restrict__ out) {
    __shared__ __align__(16) float Xs[2][8][SPAD];
    __shared__ __align__(16) float Ws[2][8][SPAD];

    const int bn = blockIdx.x;             // o tiles
    const int bm = blockIdx.y;             // row tiles
    const int tid = threadIdx.x;
    const int tx = tid & 15;
    const int ty = tid >> 4;

    const float* xg = x + (size_t)bm * 128 * IN_F;
    const float* wg = w + (size_t)bn * 128 * IN_F;

    const int lrow = tid >> 1;             // 0..127
    const int lcol = (tid & 1) * 4;        // 0 or 4

    float acc[8][8];
    #pragma unroll
    for (int m = 0; m < 8; ++m)
        #pragma unroll
        for (int n = 0; n < 8; ++n) acc[m][n] = 0.f;

    // prologue: load stage 0
    {
        float4 xv = *reinterpret_cast<const float4*>(xg + (size_t)lrow * IN_F + lcol);
        float4 wv = *reinterpret_cast<const float4*>(wg + (size_t)lrow * IN_F + lcol);
        Xs[0][lcol + 0][lrow] = xv.x; Xs[0][lcol + 1][lrow] = xv.y;
        Xs[0][lcol + 2][lrow] = xv.z; Xs[0][lcol + 3][lrow] = xv.w;
        Ws[0][lcol + 0][lrow] = wv.x; Ws[0][lcol + 1][lrow] = wv.y;
        Ws[0][lcol + 2][lrow] = wv.z; Ws[0][lcol + 3][lrow] = wv.w;
    }
    __syncthreads();

    for (int kk = 0; kk < IN_F; kk += 8) {
        const int cur = (kk >> 3) & 1;
        float4 nx, nw;
        const bool more = (kk + 8) < IN_F;
        if (more) {
            nx = *reinterpret_cast<const float4*>(xg + (size_t)lrow * IN_F + kk + 8 + lcol);
            nw = *reinterpret_cast<const float4*>(wg + (size_t)lrow * IN_F + kk + 8 + lcol);
        }

        #pragma unroll
        for (int k = 0; k < 8; ++k) {
            float xf[8], wf[8];
            *reinterpret_cast<float4*>(&xf[0]) = *reinterpret_cast<const float4*>(&Xs[cur][k][ty * 8]);
            *reinterpret_cast<float4*>(&xf[4]) = *reinterpret_cast<const float4*>(&Xs[cur][k][ty * 8 + 4]);
            *reinterpret_cast<float4*>(&wf[0]) = *reinterpret_cast<const float4*>(&Ws[cur][k][tx * 8]);
            *reinterpret_cast<float4*>(&wf[4]) = *reinterpret_cast<const float4*>(&Ws[cur][k][tx * 8 + 4]);
            #pragma unroll
            for (int m = 0; m < 8; ++m)
                #pragma unroll
                for (int n = 0; n < 8; ++n)
                    acc[m][n] = fmaf(xf[m], wf[n], acc[m][n]);
        }

        if (more) {
            const int nxt = 1 - cur;
            Xs[nxt][lcol + 0][lrow] = nx.x; Xs[nxt][lcol + 1][lrow] = nx.y;
            Xs[nxt][lcol + 2][lrow] = nx.z; Xs[nxt][lcol + 3][lrow] = nx.w;
            Ws[nxt][lcol + 0][lrow] = nw.x; Ws[nxt][lcol + 1][lrow] = nw.y;
            Ws[nxt][lcol + 2][lrow] = nw.z; Ws[nxt][lcol + 3][lrow] = nw.w;
        }
        __syncthreads();
    }

    const int r0 = bm * 128 + ty * 8;
    const int c0 = bn * 128 + tx * 8;
    #pragma unroll
    for (int m = 0; m < 8; ++m) {
        size_t base = (size_t)(r0 + m) * OUT_F + c0;
        #pragma unroll
        for (int nq = 0; nq < 2; ++nq) {
            float4 yv = *reinterpret_cast<const float4*>(&g_y[base + nq * 4]);
            float4 ov;
            ov.x = acc[m][nq * 4 + 0] + yv.x;
            ov.y = acc[m][nq * 4 + 1] + yv.y;
            ov.z = acc[m][nq * 4 + 2] + yv.z;
            ov.w = acc[m][nq * 4 + 3] + yv.w;
            *reinterpret_cast<float4*>(&out[base + nq * 4]) = ov;
        }
    }
}

// ---------------------------------------------------------------------------
extern "C" void kernel_launch(void* const* d_in, const int* in_sizes, int n_in,
                              void* d_out, int out_size) {
    const float* x    = (const float*)d_in[0];   // [2,512,4096]
    const float* w    = (const float*)d_in[1];   // [4096,4096]
    const float* spec = (const float*)d_in[2];   // [10000]
    const void*  idx  = d_in[3];                 // [2,10000] int32 or int64
    float* out = (float*)d_out;                  // [2,512,4096]
    (void)in_sizes; (void)n_in; (void)out_size;

    const int NB = (NFREQ + 255) / 256;
    k_reset  <<<1, 32>>>();
    k_detect <<<NB, 256>>>((const long long*)idx);
    k_key    <<<NB, 256>>>(idx);
    k_hclear <<<NB, 256>>>();
    k_hfill  <<<NB, 256>>>();
    k_hvalid <<<NB, 256>>>();
    k_zero   <<<((size_t)ROWS * OUT_F / 4) / 256, 256>>>();
    k_scatter<<<dim3(ROWS / 256, NFREQ), 256>>>(x, spec);
    k_wht    <<<ROWS, 256>>>();
    k_gemm   <<<dim3(OUT_F / 128, ROWS / 128), 256>>>(x, w, out);
}

// round 11
// speedup vs baseline: 4.4781x; 2.7447x over previous
#include <cuda_runtime.h>
#include <cstdint>

#define OUT_F  4096
#define IN_F   4096
#define NFREQ  10000
#define ROWS   1024
#define SCALE  2.34375f      // 150 / sqrt(4096)

// ---- GEMM tile config ----
#define BM 128
#define BN 128
#define BK 32
#define KSTAGES (IN_F / BK)          // 128
#define SROW 36                      // padded smem row (floats): conflict-free ldmatrix
#define XBYTES (BM * SROW * 4)       // 18432 B per X buffer
#define BUFBYTES (2 * XBYTES)        // X + W per buffer = 36864 B
#define SMEM_TOTAL (2 * BUFBYTES)    // 73728 B

// Scratch (static __device__ — no allocation allowed)
static __device__ float    g_y[(size_t)ROWS * OUT_F];        // 16 MB
static __device__ int      g_last[(size_t)OUT_F * IN_F];     // 64 MB hash (10k slots touched)
static __device__ unsigned g_key[NFREQ];
static __device__ int      g_valid[NFREQ];
static __device__ int      g_o[NFREQ];
static __device__ int      g_i[NFREQ];
static __device__ int      g_is32;

// ======================== PTX helpers ======================================
static __device__ __forceinline__ uint32_t smem_u32(const void* p) {
    uint32_t a;
    asm("{ .reg .u64 t; cvta.to.shared.u64 t, %1; cvt.u32.u64 %0, t; }" : "=r"(a) : "l"(p));
    return a;
}

#define LDSM_X4(r, addr) \
    asm volatile("ldmatrix.sync.aligned.m8n8.x4.shared.b16 {%0,%1,%2,%3}, [%4];" \
                 : "=r"((r)[0]), "=r"((r)[1]), "=r"((r)[2]), "=r"((r)[3]) : "r"(addr))

#define LDSM_X2(r, addr) \
    asm volatile("ldmatrix.sync.aligned.m8n8.x2.shared.b16 {%0,%1}, [%2];" \
                 : "=r"((r)[0]), "=r"((r)[1]) : "r"(addr))

#define MMA_TF32(c, a, b) \
    asm volatile("mma.sync.aligned.m16n8k8.row.col.f32.tf32.tf32.f32 " \
                 "{%0,%1,%2,%3}, {%4,%5,%6,%7}, {%8,%9}, {%0,%1,%2,%3};" \
                 : "+f"((c)[0]), "+f"((c)[1]), "+f"((c)[2]), "+f"((c)[3]) \
                 : "r"((a)[0]), "r"((a)[1]), "r"((a)[2]), "r"((a)[3]), \
                   "r"((b)[0]), "r"((b)[1]))

// ======================== setup kernels (unchanged, known-good) ============
__global__ void k_reset() { if (threadIdx.x == 0 && blockIdx.x == 0) g_is32 = 0; }

__global__ void k_detect(const long long* __restrict__ idx) {
    int k = blockIdx.x * blockDim.x + threadIdx.x;
    if (k < NFREQ) {
        unsigned long long v = (unsigned long long)idx[k];
        if (v >= (unsigned long long)OUT_F) atomicOr(&g_is32, 1);
    }
}

__global__ void k_key(const void* __restrict__ idxv) {
    int k = blockIdx.x * blockDim.x + threadIdx.x;
    if (k >= NFREQ) return;
    int o, i;
    if (g_is32) {
        const int* p = (const int*)idxv;
        o = p[k];           i = p[NFREQ + k];
    } else {
        const long long* p = (const long long*)idxv;
        o = (int)p[k];      i = (int)p[NFREQ + k];
    }
    o &= (OUT_F - 1);  i &= (IN_F - 1);
    g_o[k] = o;  g_i[k] = i;
    g_key[k] = (unsigned)o * (unsigned)IN_F + (unsigned)i;
}

__global__ void k_hclear() {
    int k = blockIdx.x * blockDim.x + threadIdx.x;
    if (k < NFREQ) g_last[g_key[k]] = 0;
}
__global__ void k_hfill() {
    int k = blockIdx.x * blockDim.x + threadIdx.x;
    if (k < NFREQ) atomicMax(&g_last[g_key[k]], k + 1);
}
__global__ void k_hvalid() {
    int k = blockIdx.x * blockDim.x + threadIdx.x;
    if (k < NFREQ) g_valid[k] = (g_last[g_key[k]] == k + 1);
}

__global__ void k_zero() {
    size_t t = (size_t)blockIdx.x * blockDim.x + threadIdx.x;
    reinterpret_cast<float4*>(g_y)[t] = make_float4(0.f, 0.f, 0.f, 0.f);
}

__global__ void k_scatter(const float* __restrict__ x, const float* __restrict__ spec) {
    int k = blockIdx.y;
    if (!g_valid[k]) return;
    int r = blockIdx.x * blockDim.x + threadIdx.x;
    int o = g_o[k];
    int i = g_i[k];
    float s = spec[k];
    atomicAdd(&g_y[(size_t)r * OUT_F + o], x[(size_t)r * IN_F + i] * s);
}

__global__ void k_wht() {
    __shared__ __align__(16) float s[OUT_F];
    int r = blockIdx.x;
    float* yr = g_y + (size_t)r * OUT_F;
    for (int j = threadIdx.x; j < OUT_F; j += blockDim.x) s[j] = yr[j];
    __syncthreads();
    for (int len = 1; len < OUT_F; len <<= 1) {
        for (int p = threadIdx.x; p < OUT_F / 2; p += blockDim.x) {
            int i0 = 2 * p - (p & (len - 1));
            int i1 = i0 + len;
            float a = s[i0], b = s[i1];
            s[i0] = a + b;
            s[i1] = a - b;
        }
        __syncthreads();
    }
    for (int j = threadIdx.x; j < OUT_F; j += blockDim.x) yr[j] = s[j] * SCALE;
}

// ======================== mma.sync tf32 GEMM ================================
// out[r,o] = (X · W^T)[r,o] + g_y[r,o]
// CTA 128x128, BK=32, 8 warps (2M x 4N), warp tile 64x32, m16n8k8 tf32.
__global__ __launch_bounds__(256, 2)
void k_gemm_mma(const float* __restrict__ x, const float* __restrict__ w,
                float* __restrict__ out) {
    extern __shared__ __align__(16) float smem[];
    const uint32_t sb = smem_u32(smem);

    const int tid  = threadIdx.x;
    const int wid  = tid >> 5;
    const int lane = tid & 31;
    const int warpM = wid >> 2;          // 0..1 -> M offset 64*warpM
    const int warpN = wid & 3;           // 0..3 -> N offset 32*warpN
    const int bn = blockIdx.x;           // 0..31
    const int bm = blockIdx.y;           // 0..7

    const float* xg = x + (size_t)bm * BM * IN_F;
    const float* wg = w + (size_t)bn * BN * IN_F;

    // Loader mapping: 1024 float4 per operand, 4 per thread.
    int lrow[4], lbyte[4];
    #pragma unroll
    for (int t = 0; t < 4; ++t) {
        int f = tid + t * 256;
        lrow[t]  = f >> 3;
        lbyte[t] = (f >> 3) * (SROW * 4) + (f & 7) * 16;   // smem byte offset
    }

    // ldmatrix per-lane byte offsets (within an X or W buffer).
    // A (.x4): row = M0 + (lane&15), col(fp32) = (lane>>4)*4
    uint32_t aoff[4];
    #pragma unroll
    for (int mt = 0; mt < 4; ++mt) {
        int r = warpM * 64 + mt * 16 + (lane & 15);
        aoff[mt] = (uint32_t)(r * SROW + (lane >> 4) * 4) * 4u;
    }
    // B (.x2): row = N0 + (lane&7), col(fp32) = ((lane>>3)&1)*4
    uint32_t boff[4];
    #pragma unroll
    for (int nt = 0; nt < 4; ++nt) {
        int r = warpN * 32 + nt * 8 + (lane & 7);
        boff[nt] = (uint32_t)(r * SROW + ((lane >> 3) & 1) * 4) * 4u;
    }

    float acc[4][4][4];
    #pragma unroll
    for (int mt = 0; mt < 4; ++mt)
        #pragma unroll
        for (int nt = 0; nt < 4; ++nt)
            #pragma unroll
            for (int j = 0; j < 4; ++j) acc[mt][nt][j] = 0.f;

    // Prologue: stage 0 direct to buffer 0.
    #pragma unroll
    for (int t = 0; t < 4; ++t) {
        float4 xv = *reinterpret_cast<const float4*>(xg + (size_t)lrow[t] * IN_F + ((tid + t * 256) & 7) * 4);
        float4 wv = *reinterpret_cast<const float4*>(wg + (size_t)lrow[t] * IN_F + ((tid + t * 256) & 7) * 4);
        *reinterpret_cast<float4*>((char*)smem + lbyte[t])          = xv;
        *reinterpret_cast<float4*>((char*)smem + XBYTES + lbyte[t]) = wv;
    }
    __syncthreads();

    for (int s = 0; s < KSTAGES; ++s) {
        const int buf = s & 1;
        const uint32_t xsu = sb + buf * BUFBYTES;
        const uint32_t wsu = xsu + XBYTES;

        float4 px[4], pw[4];
        const bool more = (s + 1) < KSTAGES;
        if (more) {
            const int kk = (s + 1) * BK;
            #pragma unroll
            for (int t = 0; t < 4; ++t) {
                int c4 = (tid + t * 256) & 7;
                px[t] = *reinterpret_cast<const float4*>(xg + (size_t)lrow[t] * IN_F + kk + c4 * 4);
                pw[t] = *reinterpret_cast<const float4*>(wg + (size_t)lrow[t] * IN_F + kk + c4 * 4);
            }
        }

        #pragma unroll
        for (int ks = 0; ks < 4; ++ks) {
            uint32_t a[4][4], b[4][2];
            #pragma unroll
            for (int mt = 0; mt < 4; ++mt) LDSM_X4(a[mt], xsu + aoff[mt] + ks * 32);
            #pragma unroll
            for (int nt = 0; nt < 4; ++nt) LDSM_X2(b[nt], wsu + boff[nt] + ks * 32);
            #pragma unroll
            for (int mt = 0; mt < 4; ++mt)
                #pragma unroll
                for (int nt = 0; nt < 4; ++nt)
                    MMA_TF32(acc[mt][nt], a[mt], b[nt]);
        }

        if (more) {
            char* xb = (char*)smem + (buf ^ 1) * BUFBYTES;
            #pragma unroll
            for (int t = 0; t < 4; ++t) {
                *reinterpret_cast<float4*>(xb + lbyte[t])          = px[t];
                *reinterpret_cast<float4*>(xb + XBYTES + lbyte[t]) = pw[t];
            }
        }
        __syncthreads();
    }

    // Epilogue: c0,c1 at (row, 2*tid4), c2,c3 at (row+8, 2*tid4); fuse +g_y.
    const int gid  = lane >> 2;
    const int tid4 = lane & 3;
    #pragma unroll
    for (int mt = 0; mt < 4; ++mt) {
        const int r0 = bm * BM + warpM * 64 + mt * 16 + gid;
        #pragma unroll
        for (int nt = 0; nt < 4; ++nt) {
            const int c = bn * BN + warpN * 32 + nt * 8 + tid4 * 2;
            size_t i0 = (size_t)r0 * OUT_F + c;
            size_t i1 = (size_t)(r0 + 8) * OUT_F + c;
            float2 y0 = *reinterpret_cast<const float2*>(&g_y[i0]);
            float2 y1 = *reinterpret_cast<const float2*>(&g_y[i1]);
            float2 o0 = make_float2(acc[mt][nt][0] + y0.x, acc[mt][nt][1] + y0.y);
            float2 o1 = make_float2(acc[mt][nt][2] + y1.x, acc[mt][nt][3] + y1.y);
            *reinterpret_cast<float2*>(&out[i0]) = o0;
            *reinterpret_cast<float2*>(&out[i1]) = o1;
        }
    }
}

// ---------------------------------------------------------------------------
extern "C" void kernel_launch(void* const* d_in, const int* in_sizes, int n_in,
                              void* d_out, int out_size) {
    const float* x    = (const float*)d_in[0];   // [2,512,4096]
    const float* w    = (const float*)d_in[1];   // [4096,4096]
    const float* spec = (const float*)d_in[2];   // [10000]
    const void*  idx  = d_in[3];                 // [2,10000] int32 or int64
    float* out = (float*)d_out;                  // [2,512,4096]
    (void)in_sizes; (void)n_in; (void)out_size;

    cudaFuncSetAttribute(k_gemm_mma, cudaFuncAttributeMaxDynamicSharedMemorySize, SMEM_TOTAL);

    const int NB = (NFREQ + 255) / 256;
    k_reset  <<<1, 32>>>();
    k_detect <<<NB, 256>>>((const long long*)idx);
    k_key    <<<NB, 256>>>(idx);
    k_hclear <<<NB, 256>>>();
    k_hfill  <<<NB, 256>>>();
    k_hvalid <<<NB, 256>>>();
    k_zero   <<<((size_t)ROWS * OUT_F / 4) / 256, 256>>>();
    k_scatter<<<dim3(ROWS / 256, NFREQ), 256>>>(x, spec);
    k_wht    <<<ROWS, 256>>>();
    k_gemm_mma<<<dim3(OUT_F / BN, ROWS / BM), 256, SMEM_TOTAL>>>(x, w, out);
}

// round 12
// speedup vs baseline: 7.0235x; 1.5684x over previous
#include <cuda_runtime.h>
#include <cuda_bf16.h>
#include <cstdint>

#define OUT_F  4096
#define IN_F   4096
#define NFREQ  10000
#define ROWS   1024
#define SCALE  2.34375f      // 150 / sqrt(4096)

// ---- GEMM tile config (bf16) ----
#define BM 128
#define BN 128
#define BK 32                        // bf16 elems per stage
#define KSTAGES (IN_F / BK)          // 128
#define SROWB 40                     // padded smem row in bf16 (80 B): conflict-free ldmatrix
#define XB_BYTES (BM * SROWB * 2)    // 10240 B per operand buffer
#define BUFB (2 * XB_BYTES)          // X + W per stage buffer = 20480 B

#define WQ ((size_t)OUT_F * IN_F / 4)   // float4 count of W
#define XQ ((size_t)ROWS * IN_F / 4)    // float4 count of X

// Scratch (static __device__ — no allocation allowed)
static __device__ float          g_y[(size_t)ROWS * OUT_F];     // 16 MB
static __device__ int            g_last[(size_t)OUT_F * IN_F];  // 64 MB hash (10k slots touched)
static __device__ __nv_bfloat16  g_wb[(size_t)OUT_F * IN_F];    // 32 MB  W in bf16
static __device__ __nv_bfloat16  g_xb[(size_t)ROWS * IN_F];     // 8 MB   X in bf16
static __device__ unsigned       g_key[NFREQ];
static __device__ int            g_o[NFREQ];
static __device__ int            g_i[NFREQ];
static __device__ unsigned       g_pk[NFREQ];                   // (o<<16)|i
static __device__ float          g_sv[NFREQ];                   // valid ? spec : 0
static __device__ int            g_is32;

// ======================== PTX helpers ======================================
static __device__ __forceinline__ uint32_t smem_u32(const void* p) {
    uint32_t a;
    asm("{ .reg .u64 t; cvta.to.shared.u64 t, %1; cvt.u32.u64 %0, t; }" : "=r"(a) : "l"(p));
    return a;
}

#define LDSM_X4(r, addr) \
    asm volatile("ldmatrix.sync.aligned.m8n8.x4.shared.b16 {%0,%1,%2,%3}, [%4];" \
                 : "=r"((r)[0]), "=r"((r)[1]), "=r"((r)[2]), "=r"((r)[3]) : "r"(addr))

#define LDSM_X2(r, addr) \
    asm volatile("ldmatrix.sync.aligned.m8n8.x2.shared.b16 {%0,%1}, [%2];" \
                 : "=r"((r)[0]), "=r"((r)[1]) : "r"(addr))

#define MMA_BF16(c, a, b) \
    asm volatile("mma.sync.aligned.m16n8k16.row.col.f32.bf16.bf16.f32 " \
                 "{%0,%1,%2,%3}, {%4,%5,%6,%7}, {%8,%9}, {%0,%1,%2,%3};" \
                 : "+f"((c)[0]), "+f"((c)[1]), "+f"((c)[2]), "+f"((c)[3]) \
                 : "r"((a)[0]), "r"((a)[1]), "r"((a)[2]), "r"((a)[3]), \
                   "r"((b)[0]), "r"((b)[1]))

// ======================== setup kernels ====================================
__global__ void k_reset() { if (threadIdx.x == 0 && blockIdx.x == 0) g_is32 = 0; }

__global__ void k_detect(const long long* __restrict__ idx) {
    int k = blockIdx.x * blockDim.x + threadIdx.x;
    if (k < NFREQ) {
        unsigned long long v = (unsigned long long)idx[k];
        if (v >= (unsigned long long)OUT_F) atomicOr(&g_is32, 1);
    }
}

// decode (o,i); pack key; clear the hash slot this key maps to (benign races: all write 0)
__global__ void k_key(const void* __restrict__ idxv) {
    int k = blockIdx.x * blockDim.x + threadIdx.x;
    if (k >= NFREQ) return;
    int o, i;
    if (g_is32) {
        const int* p = (const int*)idxv;
        o = p[k];           i = p[NFREQ + k];
    } else {
        const long long* p = (const long long*)idxv;
        o = (int)p[k];      i = (int)p[NFREQ + k];
    }
    o &= (OUT_F - 1);  i &= (IN_F - 1);
    g_o[k] = o;  g_i[k] = i;
    unsigned key = (unsigned)o * (unsigned)IN_F + (unsigned)i;
    g_key[k] = key;
    g_last[key] = 0;
}

__global__ void k_hfill() {
    int k = blockIdx.x * blockDim.x + threadIdx.x;
    if (k < NFREQ) atomicMax(&g_last[g_key[k]], k + 1);
}

// winner check (last update wins) + pack scatter payload
__global__ void k_hvalid(const float* __restrict__ spec) {
    int k = blockIdx.x * blockDim.x + threadIdx.x;
    if (k >= NFREQ) return;
    bool valid = (g_last[g_key[k]] == k + 1);
    g_pk[k] = ((unsigned)g_o[k] << 16) | (unsigned)g_i[k];
    g_sv[k] = valid ? spec[k] : 0.0f;
}

// convert W then X to bf16 (one grid covers both)
__global__ void k_cvt(const float* __restrict__ w, const float* __restrict__ x) {
    size_t t = (size_t)blockIdx.x * blockDim.x + threadIdx.x;
    if (t < WQ) {
        float4 v = reinterpret_cast<const float4*>(w)[t];
        __nv_bfloat162* d = reinterpret_cast<__nv_bfloat162*>(g_wb);
        d[2 * t]     = __floats2bfloat162_rn(v.x, v.y);
        d[2 * t + 1] = __floats2bfloat162_rn(v.z, v.w);
    } else if (t < WQ + XQ) {
        size_t u = t - WQ;
        float4 v = reinterpret_cast<const float4*>(x)[u];
        __nv_bfloat162* d = reinterpret_cast<__nv_bfloat162*>(g_xb);
        d[2 * u]     = __floats2bfloat162_rn(v.x, v.y);
        d[2 * u + 1] = __floats2bfloat162_rn(v.z, v.w);
    }
}

// ======== fused per-row: zero + sparse scatter (smem atomics) + WHT ========
__global__ __launch_bounds__(256)
void k_scatter_wht(const float* __restrict__ x) {
    __shared__ __align__(16) float xrow[IN_F];
    __shared__ __align__(16) float yrow[OUT_F];
    const int tid = threadIdx.x;
    const int r = blockIdx.x;

    const float4* xg = reinterpret_cast<const float4*>(x + (size_t)r * IN_F);
    for (int j = tid; j < IN_F / 4; j += 256)
        reinterpret_cast<float4*>(xrow)[j] = xg[j];
    for (int j = tid; j < OUT_F / 4; j += 256)
        reinterpret_cast<float4*>(yrow)[j] = make_float4(0.f, 0.f, 0.f, 0.f);
    __syncthreads();

    for (int k = tid; k < NFREQ; k += 256) {
        unsigned pk = g_pk[k];
        float s = g_sv[k];
        atomicAdd(&yrow[pk >> 16], xrow[pk & 0xFFFF] * s);
    }
    __syncthreads();

    for (int len = 1; len < OUT_F; len <<= 1) {
        for (int p = tid; p < OUT_F / 2; p += 256) {
            int i0 = 2 * p - (p & (len - 1));
            int i1 = i0 + len;
            float a = yrow[i0], b = yrow[i1];
            yrow[i0] = a + b;
            yrow[i1] = a - b;
        }
        __syncthreads();
    }

    float* yo = g_y + (size_t)r * OUT_F;
    for (int j = tid; j < OUT_F; j += 256) yo[j] = yrow[j] * SCALE;
}

// ======================== bf16 mma.sync GEMM ================================
// out[r,o] = (X · W^T)[r,o] + g_y[r,o]
// CTA 128x128, BK=32 bf16, 8 warps (2M x 4N), warp tile 64x32, m16n8k16.
__global__ __launch_bounds__(256, 2)
void k_gemm_bf16(float* __restrict__ out) {
    __shared__ __align__(16) char smem[2 * BUFB];   // 40960 B
    const uint32_t sb = smem_u32(smem);

    const int tid  = threadIdx.x;
    const int wid  = tid >> 5;
    const int lane = tid & 31;
    const int warpM = wid >> 2;
    const int warpN = wid & 3;
    const int bn = blockIdx.x;
    const int bm = blockIdx.y;

    const __nv_bfloat16* xg = g_xb + (size_t)bm * BM * IN_F;
    const __nv_bfloat16* wg = g_wb + (size_t)bn * BN * IN_F;

    // Loader mapping: stage = 128 rows x 64 B per operand = 512 uint4; 2/thread.
    int grow[2], gcol[2], sbyte[2];
    #pragma unroll
    for (int t = 0; t < 2; ++t) {
        int f = tid + t * 256;
        grow[t]  = f >> 2;
        gcol[t]  = (f & 3) * 8;                 // bf16 elems
        sbyte[t] = (f >> 2) * (SROWB * 2) + (f & 3) * 16;
    }

    // ldmatrix per-lane byte offsets within an operand buffer.
    uint32_t aoff[4];
    #pragma unroll
    for (int mt = 0; mt < 4; ++mt) {
        int rr = warpM * 64 + mt * 16 + (lane & 15);
        aoff[mt] = (uint32_t)(rr * (SROWB * 2) + (lane >> 4) * 16);
    }
    uint32_t boff[4];
    #pragma unroll
    for (int nt = 0; nt < 4; ++nt) {
        int rr = warpN * 32 + nt * 8 + (lane & 7);
        boff[nt] = (uint32_t)(rr * (SROWB * 2) + ((lane >> 3) & 1) * 16);
    }

    float acc[4][4][4];
    #pragma unroll
    for (int mt = 0; mt < 4; ++mt)
        #pragma unroll
        for (int nt = 0; nt < 4; ++nt)
            #pragma unroll
            for (int j = 0; j < 4; ++j) acc[mt][nt][j] = 0.f;

    // Prologue: stage 0 -> buffer 0
    #pragma unroll
    for (int t = 0; t < 2; ++t) {
        uint4 xv = *reinterpret_cast<const uint4*>(xg + (size_t)grow[t] * IN_F + gcol[t]);
        uint4 wv = *reinterpret_cast<const uint4*>(wg + (size_t)grow[t] * IN_F + gcol[t]);
        *reinterpret_cast<uint4*>(smem + sbyte[t])            = xv;
        *reinterpret_cast<uint4*>(smem + XB_BYTES + sbyte[t]) = wv;
    }
    __syncthreads();

    for (int s = 0; s < KSTAGES; ++s) {
        const int buf = s & 1;
        const uint32_t xsu = sb + buf * BUFB;
        const uint32_t wsu = xsu + XB_BYTES;

        uint4 px[2], pw[2];
        const bool more = (s + 1) < KSTAGES;
        if (more) {
            const int kk = (s + 1) * BK;
            #pragma unroll
            for (int t = 0; t < 2; ++t) {
                px[t] = *reinterpret_cast<const uint4*>(xg + (size_t)grow[t] * IN_F + kk + gcol[t]);
                pw[t] = *reinterpret_cast<const uint4*>(wg + (size_t)grow[t] * IN_F + kk + gcol[t]);
            }
        }

        #pragma unroll
        for (int ks = 0; ks < 2; ++ks) {           // 2 x K=16 per stage
            uint32_t a[4][4], b[4][2];
            #pragma unroll
            for (int mt = 0; mt < 4; ++mt) LDSM_X4(a[mt], xsu + aoff[mt] + ks * 32);
            #pragma unroll
            for (int nt = 0; nt < 4; ++nt) LDSM_X2(b[nt], wsu + boff[nt] + ks * 32);
            #pragma unroll
            for (int mt = 0; mt < 4; ++mt)
                #pragma unroll
                for (int nt = 0; nt < 4; ++nt)
                    MMA_BF16(acc[mt][nt], a[mt], b[nt]);
        }

        if (more) {
            char* xb = smem + (buf ^ 1) * BUFB;
            #pragma unroll
            for (int t = 0; t < 2; ++t) {
                *reinterpret_cast<uint4*>(xb + sbyte[t])            = px[t];
                *reinterpret_cast<uint4*>(xb + XB_BYTES + sbyte[t]) = pw[t];
            }
        }
        __syncthreads();
    }

    // Epilogue: c0,c1 at (row, 2*tid4), c2,c3 at (row+8); fuse +g_y.
    const int gid  = lane >> 2;
    const int tid4 = lane & 3;
    #pragma unroll
    for (int mt = 0; mt < 4; ++mt) {
        const int r0 = bm * BM + warpM * 64 + mt * 16 + gid;
        #pragma unroll
        for (int nt = 0; nt < 4; ++nt) {
            const int c = bn * BN + warpN * 32 + nt * 8 + tid4 * 2;
            size_t i0 = (size_t)r0 * OUT_F + c;
            size_t i1 = (size_t)(r0 + 8) * OUT_F + c;
            float2 y0 = *reinterpret_cast<const float2*>(&g_y[i0]);
            float2 y1 = *reinterpret_cast<const float2*>(&g_y[i1]);
            float2 o0 = make_float2(acc[mt][nt][0] + y0.x, acc[mt][nt][1] + y0.y);
            float2 o1 = make_float2(acc[mt][nt][2] + y1.x, acc[mt][nt][3] + y1.y);
            *reinterpret_cast<float2*>(&out[i0]) = o0;
            *reinterpret_cast<float2*>(&out[i1]) = o1;
        }
    }
}

// ---------------------------------------------------------------------------
extern "C" void kernel_launch(void* const* d_in, const int* in_sizes, int n_in,
                              void* d_out, int out_size) {
    const float* x    = (const float*)d_in[0];   // [2,512,4096]
    const float* w    = (const float*)d_in[1];   // [4096,4096]
    const float* spec = (const float*)d_in[2];   // [10000]
    const void*  idx  = d_in[3];                 // [2,10000] int32 or int64
    float* out = (float*)d_out;                  // [2,512,4096]
    (void)in_sizes; (void)n_in; (void)out_size;

    const int NB = (NFREQ + 255) / 256;
    k_reset  <<<1, 32>>>();
    k_detect <<<NB, 256>>>((const long long*)idx);
    k_key    <<<NB, 256>>>(idx);
    k_hfill  <<<NB, 256>>>();
    k_hvalid <<<NB, 256>>>(spec);
    k_cvt    <<<(unsigned)((WQ + XQ + 255) / 256), 256>>>(w, x);
    k_scatter_wht<<<ROWS, 256>>>(x);
    k_gemm_bf16 <<<dim3(OUT_F / BN, ROWS / BM), 256>>>(out);
}

// round 13
// speedup vs baseline: 7.1650x; 1.0201x over previous
#include <cuda_runtime.h>
#include <cuda_bf16.h>
#include <cstdint>

#define OUT_F  4096
#define IN_F   4096
#define NFREQ  10000
#define ROWS   1024
#define SCALE  2.34375f      // 150 / sqrt(4096)

// ---- GEMM tile config (bf16, 128x256) ----
#define BM 128
#define BN 256
#define BK 32                        // bf16 elems per stage
#define KSTAGES (IN_F / BK)          // 128
#define SROWB 40                     // padded smem row in bf16 (80 B): conflict-free ldmatrix
#define XB_BYTES (BM * SROWB * 2)    // 10240 B
#define WB_BYTES (BN * SROWB * 2)    // 20480 B
#define BUFB (XB_BYTES + WB_BYTES)   // 30720 B per stage
#define GEMM_SMEM (2 * BUFB)         // 61440 B

#define WQ ((size_t)OUT_F * IN_F / 4)   // float4 count of W

// Scratch (static __device__ — no allocation allowed)
static __device__ float          g_y[(size_t)ROWS * OUT_F];     // 16 MB
static __device__ int            g_last[(size_t)OUT_F * IN_F];  // 64 MB hash (10k slots touched)
static __device__ __nv_bfloat16  g_wb[(size_t)OUT_F * IN_F];    // 32 MB  W in bf16
static __device__ __nv_bfloat16  g_xb[(size_t)ROWS * IN_F];     // 8 MB   X in bf16
static __device__ unsigned       g_pk[NFREQ];                   // (o<<16)|i
static __device__ float          g_sv[NFREQ];                   // valid ? spec : 0

// ======================== PTX helpers ======================================
static __device__ __forceinline__ uint32_t smem_u32(const void* p) {
    uint32_t a;
    asm("{ .reg .u64 t; cvta.to.shared.u64 t, %1; cvt.u32.u64 %0, t; }" : "=r"(a) : "l"(p));
    return a;
}

#define LDSM_X4(r, addr) \
    asm volatile("ldmatrix.sync.aligned.m8n8.x4.shared.b16 {%0,%1,%2,%3}, [%4];" \
                 : "=r"((r)[0]), "=r"((r)[1]), "=r"((r)[2]), "=r"((r)[3]) : "r"(addr))

#define LDSM_X2(r, addr) \
    asm volatile("ldmatrix.sync.aligned.m8n8.x2.shared.b16 {%0,%1}, [%2];" \
                 : "=r"((r)[0]), "=r"((r)[1]) : "r"(addr))

#define MMA_BF16(c, a, b) \
    asm volatile("mma.sync.aligned.m16n8k16.row.col.f32.bf16.bf16.f32 " \
                 "{%0,%1,%2,%3}, {%4,%5,%6,%7}, {%8,%9}, {%0,%1,%2,%3};" \
                 : "+f"((c)[0]), "+f"((c)[1]), "+f"((c)[2]), "+f"((c)[3]) \
                 : "r"((a)[0]), "r"((a)[1]), "r"((a)[2]), "r"((a)[3]), \
                   "r"((b)[0]), "r"((b)[1]))

// ======================== fused setup (single CTA) ==========================
// Phases: detect dtype -> decode+clear hash slots -> atomicMax fill ->
// winner check + pack payload. __syncthreads orders global writes per phase
// (all traffic is within this one CTA).
__global__ __launch_bounds__(1024)
void k_prep(const void* __restrict__ idxv, const float* __restrict__ spec) {
    __shared__ int s_is32;
    __shared__ unsigned s_pk[NFREQ];   // 40 KB
    const int tid = threadIdx.x;

    if (tid == 0) s_is32 = 0;
    __syncthreads();

    // detect: reading NFREQ int64 = 80000 B = exact int32-layout buffer size
    const long long* p64 = (const long long*)idxv;
    for (int k = tid; k < NFREQ; k += 1024) {
        if ((unsigned long long)p64[k] >= (unsigned long long)OUT_F) s_is32 = 1;
    }
    __syncthreads();
    const bool is32 = (s_is32 != 0);

    // decode + clear touched hash slots
    for (int k = tid; k < NFREQ; k += 1024) {
        int o, i;
        if (is32) {
            const int* p = (const int*)idxv;
            o = p[k];           i = p[NFREQ + k];
        } else {
            o = (int)p64[k];    i = (int)p64[NFREQ + k];
        }
        o &= (OUT_F - 1);  i &= (IN_F - 1);
        unsigned pk = ((unsigned)o << 16) | (unsigned)i;
        s_pk[k] = pk;
        g_last[(unsigned)o * (unsigned)IN_F + (unsigned)i] = 0;
    }
    __syncthreads();

    // last-update-wins fill
    for (int k = tid; k < NFREQ; k += 1024) {
        unsigned pk = s_pk[k];
        atomicMax(&g_last[(pk >> 16) * (unsigned)IN_F + (pk & 0xFFFF)], k + 1);
    }
    __syncthreads();

    // winner check + payload
    for (int k = tid; k < NFREQ; k += 1024) {
        unsigned pk = s_pk[k];
        bool valid = (g_last[(pk >> 16) * (unsigned)IN_F + (pk & 0xFFFF)] == k + 1);
        g_pk[k] = pk;
        g_sv[k] = valid ? spec[k] : 0.0f;
    }
}

// ======================== W -> bf16 ========================================
__global__ void k_cvt(const float* __restrict__ w) {
    size_t t = (size_t)blockIdx.x * blockDim.x + threadIdx.x;
    if (t < WQ) {
        float4 v = reinterpret_cast<const float4*>(w)[t];
        __nv_bfloat162* d = reinterpret_cast<__nv_bfloat162*>(g_wb);
        d[2 * t]     = __floats2bfloat162_rn(v.x, v.y);
        d[2 * t + 1] = __floats2bfloat162_rn(v.z, v.w);
    }
}

// ==== fused per-row: zero + sparse scatter (smem atomics) + WHT + X->bf16 ====
__global__ __launch_bounds__(512)
void k_scatter_wht(const float* __restrict__ x) {
    __shared__ __align__(16) float xrow[IN_F];
    __shared__ __align__(16) float yrow[OUT_F];
    const int tid = threadIdx.x;
    const int r = blockIdx.x;

    const float4* xg = reinterpret_cast<const float4*>(x + (size_t)r * IN_F);
    for (int j = tid; j < IN_F / 4; j += 512)
        reinterpret_cast<float4*>(xrow)[j] = xg[j];
    for (int j = tid; j < OUT_F / 4; j += 512)
        reinterpret_cast<float4*>(yrow)[j] = make_float4(0.f, 0.f, 0.f, 0.f);
    __syncthreads();

    // X -> bf16 (row already in smem)
    {
        __nv_bfloat162* xb = reinterpret_cast<__nv_bfloat162*>(g_xb + (size_t)r * IN_F);
        for (int j = tid; j < IN_F / 2; j += 512)
            xb[j] = __floats2bfloat162_rn(xrow[2 * j], xrow[2 * j + 1]);
    }

    for (int k = tid; k < NFREQ; k += 512) {
        unsigned pk = g_pk[k];
        float s = g_sv[k];
        atomicAdd(&yrow[pk >> 16], xrow[pk & 0xFFFF] * s);
    }
    __syncthreads();

    for (int len = 1; len < OUT_F; len <<= 1) {
        for (int p = tid; p < OUT_F / 2; p += 512) {
            int i0 = 2 * p - (p & (len - 1));
            int i1 = i0 + len;
            float a = yrow[i0], b = yrow[i1];
            yrow[i0] = a + b;
            yrow[i1] = a - b;
        }
        __syncthreads();
    }

    float* yo = g_y + (size_t)r * OUT_F;
    for (int j = tid; j < OUT_F; j += 512) yo[j] = yrow[j] * SCALE;
}

// ======================== bf16 mma.sync GEMM (128x256) ======================
// out[r,o] = (X · W^T)[r,o] + g_y[r,o]
// 8 warps (2M x 4N), warp tile 64x64, m16n8k16, single wave (128 CTAs).
__global__ __launch_bounds__(256, 1)
void k_gemm_bf16(float* __restrict__ out) {
    extern __shared__ __align__(16) char smem[];
    const uint32_t sb = smem_u32(smem);

    const int tid  = threadIdx.x;
    const int wid  = tid >> 5;
    const int lane = tid & 31;
    const int warpM = wid >> 2;          // 0..1
    const int warpN = wid & 3;           // 0..3 (64 cols each)
    const int bn = blockIdx.x;           // 0..15
    const int bm = blockIdx.y;           // 0..7

    const __nv_bfloat16* xg = g_xb + (size_t)bm * BM * IN_F;
    const __nv_bfloat16* wg = g_wb + (size_t)bn * BN * IN_F;

    // Loaders: X = 512 uint4 (2/thread), W = 1024 uint4 (4/thread).
    int xrow_[2], xcol_[2], xsb_[2];
    #pragma unroll
    for (int t = 0; t < 2; ++t) {
        int f = tid + t * 256;
        xrow_[t] = f >> 2;
        xcol_[t] = (f & 3) * 8;
        xsb_[t]  = (f >> 2) * (SROWB * 2) + (f & 3) * 16;
    }
    int wrow_[4], wcol_[4], wsb_[4];
    #pragma unroll
    for (int t = 0; t < 4; ++t) {
        int f = tid + t * 256;
        wrow_[t] = f >> 2;
        wcol_[t] = (f & 3) * 8;
        wsb_[t]  = (f >> 2) * (SROWB * 2) + (f & 3) * 16;
    }

    // ldmatrix per-lane byte offsets within an operand buffer.
    uint32_t aoff[4];
    #pragma unroll
    for (int mt = 0; mt < 4; ++mt) {
        int rr = warpM * 64 + mt * 16 + (lane & 15);
        aoff[mt] = (uint32_t)(rr * (SROWB * 2) + (lane >> 4) * 16);
    }
    uint32_t boff[8];
    #pragma unroll
    for (int nt = 0; nt < 8; ++nt) {
        int rr = warpN * 64 + nt * 8 + (lane & 7);
        boff[nt] = (uint32_t)(rr * (SROWB * 2) + ((lane >> 3) & 1) * 16);
    }

    float acc[4][8][4];
    #pragma unroll
    for (int mt = 0; mt < 4; ++mt)
        #pragma unroll
        for (int nt = 0; nt < 8; ++nt)
            #pragma unroll
            for (int j = 0; j < 4; ++j) acc[mt][nt][j] = 0.f;

    // Prologue: stage 0 -> buffer 0
    #pragma unroll
    for (int t = 0; t < 2; ++t)
        *reinterpret_cast<uint4*>(smem + xsb_[t]) =
            *reinterpret_cast<const uint4*>(xg + (size_t)xrow_[t] * IN_F + xcol_[t]);
    #pragma unroll
    for (int t = 0; t < 4; ++t)
        *reinterpret_cast<uint4*>(smem + XB_BYTES + wsb_[t]) =
            *reinterpret_cast<const uint4*>(wg + (size_t)wrow_[t] * IN_F + wcol_[t]);
    __syncthreads();

    for (int s = 0; s < KSTAGES; ++s) {
        const int buf = s & 1;
        const uint32_t xsu = sb + buf * BUFB;
        const uint32_t wsu = xsu + XB_BYTES;

        uint4 px[2], pw[4];
        const bool more = (s + 1) < KSTAGES;
        if (more) {
            const int kk = (s + 1) * BK;
            #pragma unroll
            for (int t = 0; t < 2; ++t)
                px[t] = *reinterpret_cast<const uint4*>(xg + (size_t)xrow_[t] * IN_F + kk + xcol_[t]);
            #pragma unroll
            for (int t = 0; t < 4; ++t)
                pw[t] = *reinterpret_cast<const uint4*>(wg + (size_t)wrow_[t] * IN_F + kk + wcol_[t]);
        }

        #pragma unroll
        for (int ks = 0; ks < 2; ++ks) {           // 2 x K=16 per stage
            uint32_t a[4][4], b[8][2];
            #pragma unroll
            for (int mt = 0; mt < 4; ++mt) LDSM_X4(a[mt], xsu + aoff[mt] + ks * 32);
            #pragma unroll
            for (int nt = 0; nt < 8; ++nt) LDSM_X2(b[nt], wsu + boff[nt] + ks * 32);
            #pragma unroll
            for (int mt = 0; mt < 4; ++mt)
                #pragma unroll
                for (int nt = 0; nt < 8; ++nt)
                    MMA_BF16(acc[mt][nt], a[mt], b[nt]);
        }

        if (more) {
            char* xb = smem + (buf ^ 1) * BUFB;
            #pragma unroll
            for (int t = 0; t < 2; ++t)
                *reinterpret_cast<uint4*>(xb + xsb_[t]) = px[t];
            #pragma unroll
            for (int t = 0; t < 4; ++t)
                *reinterpret_cast<uint4*>(xb + XB_BYTES + wsb_[t]) = pw[t];
        }
        __syncthreads();
    }

    // Epilogue: c0,c1 at (row, 2*tid4), c2,c3 at (row+8); fuse +g_y.
    const int gid  = lane >> 2;
    const int tid4 = lane & 3;
    #pragma unroll
    for (int mt = 0; mt < 4; ++mt) {
        const int r0 = bm * BM + warpM * 64 + mt * 16 + gid;
        #pragma unroll
        for (int nt = 0; nt < 8; ++nt) {
            const int c = bn * BN + warpN * 64 + nt * 8 + tid4 * 2;
            size_t i0 = (size_t)r0 * OUT_F + c;
            size_t i1 = (size_t)(r0 + 8) * OUT_F + c;
            float2 y0 = *reinterpret_cast<const float2*>(&g_y[i0]);
            float2 y1 = *reinterpret_cast<const float2*>(&g_y[i1]);
            float2 o0 = make_float2(acc[mt][nt][0] + y0.x, acc[mt][nt][1] + y0.y);
            float2 o1 = make_float2(acc[mt][nt][2] + y1.x, acc[mt][nt][3] + y1.y);
            *reinterpret_cast<float2*>(&out[i0]) = o0;
            *reinterpret_cast<float2*>(&out[i1]) = o1;
        }
    }
}

// ---------------------------------------------------------------------------
extern "C" void kernel_launch(void* const* d_in, const int* in_sizes, int n_in,
                              void* d_out, int out_size) {
    const float* x    = (const float*)d_in[0];   // [2,512,4096]
    const float* w    = (const float*)d_in[1];   // [4096,4096]
    const float* spec = (const float*)d_in[2];   // [10000]
    const void*  idx  = d_in[3];                 // [2,10000] int32 or int64
    float* out = (float*)d_out;                  // [2,512,4096]
    (void)in_sizes; (void)n_in; (void)out_size;

    cudaFuncSetAttribute(k_gemm_bf16, cudaFuncAttributeMaxDynamicSharedMemorySize, GEMM_SMEM);

    k_prep       <<<1, 1024>>>(idx, spec);
    k_cvt        <<<(unsigned)((WQ + 511) / 512), 512>>>(w);
    k_scatter_wht<<<ROWS, 512>>>(x);
    k_gemm_bf16  <<<dim3(OUT_F / BN, ROWS / BM), 256, GEMM_SMEM>>>(out);
}